// round 17
// baseline (speedup 1.0000x reference)
#include <cuda_runtime.h>
#include <cstdint>

#define NB   4
#define NT   4096
#define DIN  64
#define DM   256
#define BT   (NB*NT)
#define BLK  128
#define HALF 64
#define NCHB (NT/BLK)            // 32
#define NBLK (BT/BLK)            // 128 blocks, one wave
#define HSS  266                 // h tile row stride (even -> aligned float2; 266%32=10)

// -------- globals --------
__device__ float g_S[NBLK*DM];
__device__ float g_Zc[NBLK];
__device__ float g_Ac[NBLK];
__device__ int   g_flag[NBLK];
__device__ int   g_epoch;

__global__ void bump_epoch_kernel() { g_epoch = g_epoch + 1; }

// -------- smem float offsets --------
#define TS   68                  // tf32 tile row stride (floats); (68*g+k)%32 = 4g+k -> conflict-free frags
#define XH   0                   // x_hi  [128][68]
#define XL   (XH + 128*TS)       // x_lo
#define WH   (XL + 128*TS)       // W_hi  [256][68]
#define WLo  (WH + 256*TS)       // W_lo
#define TAIL (WLo + 256*TS)      // 52224
#define O_DS   (TAIL)            // [128]
#define O_BIAS (TAIL+128)        // [256]
#define O_SHS0 (TAIL+384)        // [256]
#define O_SA   (TAIL+640)        // [32]
#define O_SZ   (TAIL+672)        // [32]
#define O_SAP  (TAIL+704)        // [32]
#define O_SSC  (TAIL+736)        // [4]
#define GSMEM ((TAIL+740)*4)     // 211,856 B (1 CTA/SM)

static __device__ __forceinline__ uint32_t f2tf32(float f) {
    uint32_t u; asm("cvt.rna.tf32.f32 %0, %1;" : "=r"(u) : "f"(f)); return u;
}
#define MMA_TF32(d, a, b)                                                              \
    asm volatile("mma.sync.aligned.m16n8k8.row.col.f32.tf32.tf32.f32 "                 \
                 "{%0,%1,%2,%3}, {%4,%5,%6,%7}, {%8,%9}, {%0,%1,%2,%3};"               \
                 : "+f"((d)[0]), "+f"((d)[1]), "+f"((d)[2]), "+f"((d)[3])              \
                 : "r"((a)[0]), "r"((a)[1]), "r"((a)[2]), "r"((a)[3]),                 \
                   "r"((b)[0]), "r"((b)[1]))

__global__ __launch_bounds__(512, 1)
void fused_kernel(const float* __restrict__ x, const float* __restrict__ tau,
                  const float* __restrict__ W, const float* __restrict__ bias,
                  const float* __restrict__ lamb, float* __restrict__ out)
{
    extern __shared__ float sm[];
    float* hs   = sm;                      // h tile overlays tf32 tiles after MMA
    float* ds   = sm + O_DS;
    float* sbias= sm + O_BIAS;
    float* shS0 = sm + O_SHS0;
    float* sA   = sm + O_SA;
    float* sZ   = sm + O_SZ;
    float* sAp  = sm + O_SAP;
    float* ssc  = sm + O_SSC;

    __shared__ int s_epoch;

    const int t    = threadIdx.x;
    const int wid  = t >> 5;
    const int lid  = t & 31;
    const int blk  = blockIdx.x;
    const int row0 = blk * BLK;
    const int kk   = blk & (NCHB-1);
    const int base = blk - kk;
    const int half = t >> 8;
    const int m    = t & 255;

    if (t == 0) s_epoch = g_epoch;

    // ---- decays + bias staging (tail region disjoint from tiles) ----
    if (t < BLK) {
        float lam = fmaxf(__ldg(&lamb[0]), 0.0f);
        ds[t] = __expf(-lam * __ldg(&tau[row0 + t]));
    }
    if (t < DM) sbias[t] = __ldg(&bias[t]);

    // ---- fill x tiles (hi/lo tf32), row-major stride 68 ----
    {
        const int r = t >> 2, q = t & 3;             // 16 floats per thread
        const float* xr = x + (size_t)(row0 + r)*DIN + 16*q;
        #pragma unroll
        for (int f = 0; f < 4; f++) {
            float4 v = *(const float4*)&xr[4*f];
            uint4 h4, l4;
            h4.x = f2tf32(v.x); l4.x = f2tf32(v.x - __uint_as_float(h4.x));
            h4.y = f2tf32(v.y); l4.y = f2tf32(v.y - __uint_as_float(h4.y));
            h4.z = f2tf32(v.z); l4.z = f2tf32(v.z - __uint_as_float(h4.z));
            h4.w = f2tf32(v.w); l4.w = f2tf32(v.w - __uint_as_float(h4.w));
            int off = r*TS + 16*q + 4*f;
            *(uint4*)&sm[XH + off] = h4;
            *(uint4*)&sm[XL + off] = l4;
        }
    }
    // ---- fill W tiles (hi/lo tf32), row-major stride 68 ----
    {
        const int n = t >> 1, q = t & 1;             // 32 floats per thread
        const float* wr = W + (size_t)n*DIN + 32*q;
        #pragma unroll
        for (int f = 0; f < 8; f++) {
            float4 v = *(const float4*)&wr[4*f];
            uint4 h4, l4;
            h4.x = f2tf32(v.x); l4.x = f2tf32(v.x - __uint_as_float(h4.x));
            h4.y = f2tf32(v.y); l4.y = f2tf32(v.y - __uint_as_float(h4.y));
            h4.z = f2tf32(v.z); l4.z = f2tf32(v.z - __uint_as_float(h4.z));
            h4.w = f2tf32(v.w); l4.w = f2tf32(v.w - __uint_as_float(h4.w));
            int off = n*TS + 32*q + 4*f;
            *(uint4*)&sm[WH  + off] = h4;
            *(uint4*)&sm[WLo + off] = l4;
        }
    }
    __syncthreads();

    // ---- 3xTF32 mma.sync GEMM: D = Ah*Bh + Al*Bh + Ah*Bl ----
    // warp layout: m-block (wid&3)*32 (2 m16 tiles), n-chunk (wid>>2)*64 (8 n8 tiles)
    const int m0 = (wid & 3) * 32;
    const int n0 = (wid >> 2) * 64;
    const int g   = lid >> 2;     // 0..7
    const int tig = lid & 3;      // 0..3

    float dacc[2][8][4];
    #pragma unroll
    for (int mt = 0; mt < 2; mt++)
        #pragma unroll
        for (int nt = 0; nt < 8; nt++)
            #pragma unroll
            for (int c = 0; c < 4; c++) dacc[mt][nt][c] = 0.0f;

    for (int s = 0; s < 8; s++) {
        const int k0 = 8*s;
        uint32_t ah[2][4], al[2][4], bf[8][2];
        #pragma unroll
        for (int mt = 0; mt < 2; mt++) {
            const float* ap = &sm[XH + (m0 + 16*mt + g)*TS + k0 + tig];
            ah[mt][0] = __float_as_uint(ap[0]);
            ah[mt][1] = __float_as_uint(ap[8*TS]);
            ah[mt][2] = __float_as_uint(ap[4]);
            ah[mt][3] = __float_as_uint(ap[8*TS + 4]);
            const float* lp = &sm[XL + (m0 + 16*mt + g)*TS + k0 + tig];
            al[mt][0] = __float_as_uint(lp[0]);
            al[mt][1] = __float_as_uint(lp[8*TS]);
            al[mt][2] = __float_as_uint(lp[4]);
            al[mt][3] = __float_as_uint(lp[8*TS + 4]);
        }
        #pragma unroll
        for (int nt = 0; nt < 8; nt++) {
            const float* bp = &sm[WH + (n0 + 8*nt + g)*TS + k0 + tig];
            bf[nt][0] = __float_as_uint(bp[0]);
            bf[nt][1] = __float_as_uint(bp[4]);
        }
        #pragma unroll
        for (int mt = 0; mt < 2; mt++)
            #pragma unroll
            for (int nt = 0; nt < 8; nt++) MMA_TF32(dacc[mt][nt], ah[mt], bf[nt]);
        #pragma unroll
        for (int mt = 0; mt < 2; mt++)
            #pragma unroll
            for (int nt = 0; nt < 8; nt++) MMA_TF32(dacc[mt][nt], al[mt], bf[nt]);
        #pragma unroll
        for (int nt = 0; nt < 8; nt++) {          // reuse bf regs for B_lo
            const float* bp = &sm[WLo + (n0 + 8*nt + g)*TS + k0 + tig];
            bf[nt][0] = __float_as_uint(bp[0]);
            bf[nt][1] = __float_as_uint(bp[4]);
        }
        #pragma unroll
        for (int mt = 0; mt < 2; mt++)
            #pragma unroll
            for (int nt = 0; nt < 8; nt++) MMA_TF32(dacc[mt][nt], ah[mt], bf[nt]);
    }
    __syncthreads();   // tiles dead -> h tile overlay

    // ---- epilogue: +bias, elu -> hs ----
    #pragma unroll
    for (int mt = 0; mt < 2; mt++) {
        #pragma unroll
        for (int nt = 0; nt < 8; nt++) {
            int rr = m0 + 16*mt + g;
            int cc = n0 + 8*nt + 2*tig;
            float b0f = sbias[cc], b1f = sbias[cc+1];
            float v0 = dacc[mt][nt][0] + b0f;
            float v1 = dacc[mt][nt][1] + b1f;
            float v2 = dacc[mt][nt][2] + b0f;
            float v3 = dacc[mt][nt][3] + b1f;
            v0 = (v0 > 0.0f) ? v0 : (__expf(v0) - 1.0f);
            v1 = (v1 > 0.0f) ? v1 : (__expf(v1) - 1.0f);
            v2 = (v2 > 0.0f) ? v2 : (__expf(v2) - 1.0f);
            v3 = (v3 > 0.0f) ? v3 : (__expf(v3) - 1.0f);
            *(float2*)&hs[rr*HSS + cc]       = make_float2(v0, v1);
            *(float2*)&hs[(rr + 8)*HSS + cc] = make_float2(v2, v3);
        }
    }
    __syncthreads();

    // ---- local scan, halves of 64 rows (R6 form) ----
    const int i0 = half * HALF;
    float S = 0.0f, Z = 0.0f, A = 1.0f;
    #pragma unroll 8
    for (int i = 0; i < HALF; i++) {
        float d = ds[i0 + i];
        S = fmaf(S, d, hs[(i0 + i)*HSS + m]);
        Z = fmaf(Z, d, 1.0f);
        A *= d;
    }
    if (half == 0) {
        shS0[m] = S;
        if (m == 0) { ssc[0] = Z; ssc[1] = A; }
    }
    __syncthreads();

    // ---- half-1 publishes combined block aggregate ----
    const int e = s_epoch;
    if (half == 1) {
        g_S[(size_t)blk*DM + m] = fmaf(shS0[m], A, S);
        if (m == 0) {
            g_Zc[blk] = fmaf(ssc[0], A, Z);
            g_Ac[blk] = ssc[1] * A;
        }
        __threadfence();
    }
    __syncthreads();
    if (t == 0) *(volatile int*)&g_flag[blk] = e;   // release

    // ---- parallel lookback ----
    float cS = 0.0f, cZ = 0.0f;
    if (kk > 0) {
        int ok;
        do {
            ok = (t < kk) ? (*(volatile int*)&g_flag[base + t] == e) : 1;
        } while (!__syncthreads_and(ok));
        __threadfence();   // acquire

        if (t < kk) { sA[t] = g_Ac[base + t]; sZ[t] = g_Zc[base + t]; }
        __syncthreads();
        if (t == 0) {
            float Ap = 1.0f, z = 0.0f;
            for (int j = kk - 1; j >= 0; j--) {
                sAp[j] = Ap;
                z = fmaf(Ap, sZ[j], z);
                Ap *= sA[j];
            }
            ssc[2] = z;
        }
        __syncthreads();

        const float* gsb = g_S + (size_t)base*DM + m;
        #pragma unroll 4
        for (int j = 0; j < kk; j++)
            cS = fmaf(sAp[j], __ldg(&gsb[(size_t)j*DM]), cS);
        cZ = ssc[2];
    }

    // ---- finalize per half, write out ----
    float Sf, Zf;
    if (half == 0) { Sf = cS; Zf = cZ; }
    else {
        float A0 = ssc[1];
        Sf = fmaf(cS, A0, shS0[m]);
        Zf = fmaf(cZ, A0, ssc[0]);
    }
    float* op = out + (size_t)(row0 + i0)*DM + m;
    #pragma unroll 8
    for (int i = 0; i < HALF; i++) {
        float d = ds[i0 + i];
        Sf = fmaf(Sf, d, hs[(i0 + i)*HSS + m]);
        Zf = fmaf(Zf, d, 1.0f);
        op[(size_t)i*DM] = __fdividef(Sf, Zf);
    }
}

// -------- launch --------
extern "C" void kernel_launch(void* const* d_in, const int* in_sizes, int n_in,
                              void* d_out, int out_size)
{
    const float* x    = (const float*)d_in[0];
    const float* tau  = (const float*)d_in[1];
    const float* W    = (const float*)d_in[2];
    const float* bias = (const float*)d_in[3];
    const float* lamb = (const float*)d_in[4];
    // beta (d_in[5]) cancels in softmax (constant per row)
    float* out = (float*)d_out;

    cudaFuncSetAttribute(fused_kernel,
                         cudaFuncAttributeMaxDynamicSharedMemorySize, GSMEM);

    bump_epoch_kernel<<<1, 1>>>();
    fused_kernel<<<NBLK, 512, GSMEM>>>(x, tau, W, bias, lamb, out);
}